// round 9
// baseline (speedup 1.0000x reference)
#include <cuda_runtime.h>
#include <math.h>

// Problem constants
#define BB   4
#define NN   6
#define FD   256
#define DD   128
#define HF   64
#define WF   120
#define PP   (HF*WF)          // 7680
#define IMG_H 480.0f
#define IMG_W 960.0f
#define EPS_LN 1e-5f
#define EPS_BN 1e-5f

typedef unsigned long long u64;

// Packed fp32x2 FMA (sm_103a FFMA2 path; PTX-only, ptxas never auto-fuses)
#define FMA_F32X2(d, a, b, c) \
    asm("fma.rn.f32x2 %0, %1, %2, %3;" : "=l"(d) : "l"(a), "l"(b), "l"(c))
#define UNPACK_F32X2(lo, hi, in) \
    asm("mov.b64 {%0, %1}, %2;" : "=f"(lo), "=f"(hi) : "l"(in))

__device__ __forceinline__ u64 packdup(float x) {
    u64 r; asm("mov.b64 %0, {%1, %1};" : "=l"(r) : "f"(x)); return r;
}

// Scratch (device globals; no allocation allowed)
__device__ float g_val[(size_t)BB*NN*PP*DD];   // conv output, layout (b,n,p,d)  ~94.4 MB
__device__ float g_z  [(size_t)BB*PP*DD];      // attention output, layout (b,p,d) ~15.7 MB
__device__ float g_Hm [BB*NN*9];               // homographies

// ---------------------------------------------------------------------------
// Kernel 0: homography matrices Hm = I_src @ (R - T nv^T / dis) @ I_tar_inv
// ---------------------------------------------------------------------------
__global__ void k_hm(const float* __restrict__ I_src, const float* __restrict__ I_tar_inv,
                     const float* __restrict__ E, const float* __restrict__ dis_p,
                     const float* __restrict__ nv)
{
    int t = threadIdx.x;
    if (t >= BB*NN) return;
    int b = t / NN;
    const float* e  = E + (size_t)t*16;
    const float* nb = nv + (size_t)b*3;
    float dis = dis_p[0];

    float M[9];
    #pragma unroll
    for (int i=0;i<3;i++)
        #pragma unroll
        for (int j=0;j<3;j++)
            M[i*3+j] = e[i*4+j] - e[i*4+3]*nb[j]/dis;

    const float* Ti = I_tar_inv + (size_t)b*9;
    float A[9];
    #pragma unroll
    for (int i=0;i<3;i++)
        #pragma unroll
        for (int j=0;j<3;j++)
            A[i*3+j] = M[i*3+0]*Ti[0*3+j] + M[i*3+1]*Ti[1*3+j] + M[i*3+2]*Ti[2*3+j];

    const float* Is = I_src + (size_t)t*9;
    #pragma unroll
    for (int i=0;i<3;i++)
        #pragma unroll
        for (int j=0;j<3;j++)
            g_Hm[t*9 + i*3+j] = Is[i*3+0]*A[0*3+j] + Is[i*3+1]*A[1*3+j] + Is[i*3+2]*A[2*3+j];
}

// ---------------------------------------------------------------------------
// Kernel 1: val[b,n,p,o] = sum_f conv_w[o,f] * relu(bn(feature[b,n,f,p]))
// Tiled fp32 GEMM, FFMA2-packed over p-pairs; float4-vectorized staging.
// ---------------------------------------------------------------------------
__global__ __launch_bounds__(256) void k_conv(const float* __restrict__ feature,
                                              const float* __restrict__ conv_w,
                                              const float* __restrict__ bn_g,
                                              const float* __restrict__ bn_b,
                                              const float* __restrict__ bn_m,
                                              const float* __restrict__ bn_v)
{
    __shared__ float fs[16][128];        // [k][p]  8 KB
    __shared__ u64   ws2[16][129];       // [k][o] packed (w,w), pad=1  16.1 KB
    __shared__ float sc[FD], sh[FD];     // 2 KB

    const int blk   = blockIdx.x;             // 0 .. 24*60-1
    const int ptile = blk % (PP/128);         // 60 tiles
    const int bnidx = blk / (PP/128);         // b*NN + n
    const int p0    = ptile * 128;
    const int tid   = threadIdx.x;

    // BN scale/shift precompute: 256 threads cover FD=256 exactly
    {
        float s = bn_g[tid] * rsqrtf(bn_v[tid] + EPS_BN);
        sc[tid] = s;
        sh[tid] = bn_b[tid] - bn_m[tid] * s;
    }
    __syncthreads();

    const float* fbase = feature + (size_t)bnidx * FD * PP;
    const int to = (tid >> 4) * 8;    // o base
    const int tp = (tid & 15) * 8;    // p base (4 pairs)

    u64 acc2[4][8];                   // [p-pair][o]; each u64 = (p even, p odd)
    #pragma unroll
    for (int j=0;j<4;j++)
        #pragma unroll
        for (int i=0;i<8;i++) acc2[j][i] = 0ull;

    for (int kk=0; kk<FD; kk+=16) {
        // stage feature tile (BN+ReLU), float4 loads: 512 float4 / 256 thr = 2
        #pragma unroll
        for (int i=0;i<2;i++) {
            int e  = tid + i*256;
            int r  = e >> 5, c4 = e & 31;
            float4 v = *(const float4*)(fbase + (size_t)(kk+r)*PP + p0 + c4*4);
            float s = sc[kk+r], h = sh[kk+r];
            v.x = fmaxf(v.x*s + h, 0.f);
            v.y = fmaxf(v.y*s + h, 0.f);
            v.z = fmaxf(v.z*s + h, 0.f);
            v.w = fmaxf(v.w*s + h, 0.f);
            *(float4*)&fs[r][c4*4] = v;
        }
        // stage weight tile as pre-broadcast (w,w) pairs; float4 loads
        #pragma unroll
        for (int i=0;i<2;i++) {
            int e  = tid + i*256;
            int o  = e >> 2, k4 = e & 3;
            float4 w = *(const float4*)(conv_w + (size_t)o*FD + kk + k4*4);
            ws2[k4*4+0][o] = packdup(w.x);
            ws2[k4*4+1][o] = packdup(w.y);
            ws2[k4*4+2][o] = packdup(w.z);
            ws2[k4*4+3][o] = packdup(w.w);
        }
        __syncthreads();

        #pragma unroll
        for (int k=0;k<16;k++) {
            ulonglong2 fa = *(const ulonglong2*)&fs[k][tp];     // (p0,p1),(p2,p3)
            ulonglong2 fb = *(const ulonglong2*)&fs[k][tp+4];   // (p4,p5),(p6,p7)
            const u64* wrow = &ws2[k][to];
            #pragma unroll
            for (int i=0;i<8;i++) {
                u64 w2 = wrow[i];                               // LDS.64 broadcast
                FMA_F32X2(acc2[0][i], w2, fa.x, acc2[0][i]);
                FMA_F32X2(acc2[1][i], w2, fa.y, acc2[1][i]);
                FMA_F32X2(acc2[2][i], w2, fb.x, acc2[2][i]);
                FMA_F32X2(acc2[3][i], w2, fb.y, acc2[3][i]);
            }
        }
        __syncthreads();
    }

    // store: g_val[(bnidx*PP + p)*DD + o]; unpack pairs -> two rows per j
    float* obase = g_val + ((size_t)bnidx*PP + p0) * DD;
    #pragma unroll
    for (int j=0;j<4;j++) {
        float lo[8], hi[8];
        #pragma unroll
        for (int i=0;i<8;i++) { UNPACK_F32X2(lo[i], hi[i], acc2[j][i]); }
        float* row0 = obase + (size_t)(tp + 2*j    )*DD + to;
        float* row1 = obase + (size_t)(tp + 2*j + 1)*DD + to;
        *(float4*)(row0)   = make_float4(lo[0],lo[1],lo[2],lo[3]);
        *(float4*)(row0+4) = make_float4(lo[4],lo[5],lo[6],lo[7]);
        *(float4*)(row1)   = make_float4(hi[0],hi[1],hi[2],hi[3]);
        *(float4*)(row1+4) = make_float4(hi[4],hi[5],hi[6],hi[7]);
    }
}

// ---------------------------------------------------------------------------
// Kernel 2: homography warp + bilinear sample + cosine attention over N views
// 256-thread block = 4 pixels x 64 threads; each thread = channel PAIR (float2)
// ---------------------------------------------------------------------------
__global__ __launch_bounds__(256) void k_att()
{
    __shared__ float shm[NN*9];
    __shared__ float red[8][13];

    const int grp = threadIdx.x >> 6;          // pixel slot 0..3
    const int t64 = threadIdx.x & 63;          // channel-pair id
    const int pix = blockIdx.x*4 + grp;
    const int b = pix / PP;
    const int p = pix % PP;

    if (threadIdx.x < NN*9) shm[threadIdx.x] = g_Hm[b*NN*9 + threadIdx.x];
    __syncthreads();

    const int px = p % WF, py = p / WF;
    const float X = ((float)px / (float)(WF-1)) * IMG_W;
    const float Y = ((float)py / (float)(HF-1)) * IMG_H;

    const float2* vb2 = (const float2*)g_val + (size_t)b*NN*PP*(DD/2);
    const float2 qv = vb2[(size_t)p*(DD/2) + t64];   // view 0 = query

    float2 s2[NN];
    float validf[NN];

    #pragma unroll
    for (int n=0;n<NN;n++) {
        const float* Hh = shm + n*9;
        float hx = Hh[0]*X + Hh[1]*Y + Hh[2];
        float hy = Hh[3]*X + Hh[4]*Y + Hh[5];
        float hz = Hh[6]*X + Hh[7]*Y + Hh[8];
        float inv = 1.0f / hz;
        float u = (hx*inv) * ((float)WF / IMG_W);
        float v = (hy*inv) * ((float)HF / IMG_H);

        float x0 = floorf(u), y0 = floorf(v);
        float ax = 0.f, ay = 0.f;
        #pragma unroll
        for (int dx=0;dx<2;dx++) {
            #pragma unroll
            for (int dy=0;dy<2;dy++) {
                float cx = x0 + (float)dx, cy = y0 + (float)dy;
                float wgt = (1.0f - fabsf(u-cx)) * (1.0f - fabsf(v-cy));
                bool inb = (cx >= 0.f) && (cx <= (float)(WF-1)) &&
                           (cy >= 0.f) && (cy <= (float)(HF-1));
                int icx = (int)fminf(fmaxf(cx,0.f),(float)(WF-1));
                int icy = (int)fminf(fmaxf(cy,0.f),(float)(HF-1));
                float2 g = vb2[((size_t)n*PP + icy*WF + icx)*(DD/2) + t64];
                float wf = inb ? wgt : 0.f;
                ax += g.x * wf;
                ay += g.y * wf;
            }
        }
        s2[n] = make_float2(ax, ay);
        validf[n] = ((u >= 0.f) && (u <= (float)(WF-1)) &&
                     (v >= 0.f) && (v <= (float)(HF-1))) ? 1.f : 0.f;
    }

    // batched reduction of 13 quantities over the pixel's 64 threads:
    // [0..5] = sum s_n^2 ; [6..11] = sum qv*s_n ; [12] = sum qv^2
    float part[13];
    #pragma unroll
    for (int n=0;n<NN;n++) {
        part[n]   = s2[n].x*s2[n].x + s2[n].y*s2[n].y;
        part[6+n] = qv.x*s2[n].x   + qv.y*s2[n].y;
    }
    part[12] = qv.x*qv.x + qv.y*qv.y;

    #pragma unroll
    for (int o=16;o>0;o>>=1)
        #pragma unroll
        for (int i=0;i<13;i++)
            part[i] += __shfl_xor_sync(0xffffffffu, part[i], o);

    const int wid = threadIdx.x >> 5;          // 2*grp + warp-in-pixel
    if ((threadIdx.x & 31) == 0)
        #pragma unroll
        for (int i=0;i<13;i++) red[wid][i] = part[i];
    __syncthreads();

    float tot[13];
    #pragma unroll
    for (int i=0;i<13;i++)
        tot[i] = red[2*grp][i] + red[2*grp+1][i];

    const float qn = fmaxf(sqrtf(tot[12]), 1e-12f);
    float dotv[NN];
    #pragma unroll
    for (int n=0;n<NN;n++) {
        float nn = fmaxf(sqrtf(tot[n]), 1e-12f);
        dotv[n] = (tot[6+n] / (qn*nn)) * validf[n];
    }
    float m = dotv[0];
    #pragma unroll
    for (int n=1;n<NN;n++) m = fmaxf(m, dotv[n]);
    float esum = 0.f, e[NN];
    #pragma unroll
    for (int n=0;n<NN;n++) { e[n] = expf(dotv[n]-m); esum += e[n]; }
    float inv_es = 1.0f / esum;

    float zx = qv.x, zy = qv.y;
    #pragma unroll
    for (int n=0;n<NN;n++) {
        float a = e[n]*inv_es;
        zx += a*s2[n].x;
        zy += a*s2[n].y;
    }

    float2* gz2 = (float2*)g_z;
    gz2[((size_t)b*PP + p)*(DD/2) + t64] = make_float2(zx, zy);
}

// ---------------------------------------------------------------------------
// Kernel 3: LN1 -> MLP(128->256 gelu ->128) + residual(from LN1 out) -> LN2
// TOK=32 tokens/block via DYNAMIC shared memory (70.1 KB): halves W1/W2
// L2->L1 weight traffic per token and doubles FFMA2 ILP.
// Layout (floats): zs[32][129] | xt[128][36] | ht[256][36]
// ---------------------------------------------------------------------------
#define TOK 32
#define TPAD 36
#define ZS_OFF 0
#define XT_OFF (TOK*129)              // 4128
#define HT_OFF (XT_OFF + 128*TPAD)    // 8736
#define MLP_SMEM_FLOATS (HT_OFF + 256*TPAD)   // 17952 floats = 71808 B
#define ZS(t,k) smem[ZS_OFF + (t)*129 + (k)]
#define XT(k,t) smem[XT_OFF + (k)*TPAD + (t)]
#define HT(j,t) smem[HT_OFF + (j)*TPAD + (t)]

__global__ __launch_bounds__(256) void k_mlp(const float* __restrict__ ln1g,
                                             const float* __restrict__ ln1b,
                                             const float* __restrict__ w1,
                                             const float* __restrict__ b1,
                                             const float* __restrict__ w2,
                                             const float* __restrict__ b2,
                                             const float* __restrict__ ln2g,
                                             const float* __restrict__ ln2b,
                                             float* __restrict__ out)
{
    extern __shared__ float smem[];

    const int blk = blockIdx.x;               // b*(PP/TOK)+chunk
    const int b   = blk / (PP/TOK);
    const int p0  = (blk % (PP/TOK)) * TOK;
    const int tid = threadIdx.x;
    const int lane = tid & 31, w = tid >> 5;  // 8 warps

    const float* zbase = g_z + ((size_t)b*PP + p0) * DD;
    #pragma unroll
    for (int i=0;i<16;i++) {                  // 4096 elems / 256 threads
        int e = tid + i*256;
        int t = e >> 7, k = e & 127;
        ZS(t,k) = zbase[(size_t)t*DD + k];
    }
    __syncthreads();

    // LN1: warp w -> tokens 4w..4w+3; write token-minor XT(k,t)
    #pragma unroll
    for (int tt=0;tt<4;tt++) {
        int t = w*4 + tt;
        float sum=0.f, sq=0.f;
        #pragma unroll
        for (int j=0;j<4;j++) { float v = ZS(t, lane + j*32); sum += v; sq += v*v; }
        #pragma unroll
        for (int o=16;o>0;o>>=1) {
            sum += __shfl_xor_sync(0xffffffffu,sum,o);
            sq  += __shfl_xor_sync(0xffffffffu,sq,o);
        }
        float mu = sum*(1.f/128.f);
        float var = sq*(1.f/128.f) - mu*mu;
        float rs = rsqrtf(var + EPS_LN);
        #pragma unroll
        for (int j=0;j<4;j++) {
            int k = lane + j*32;
            XT(k,t) = (ZS(t,k)-mu)*rs*ln1g[k] + ln1b[k];
        }
    }
    __syncthreads();

    // W1: thread = col c; 16 token-pair FFMA2 accumulators
    {
        const int c = tid;
        u64 a1[16];
        u64 binit = packdup(b1[c]);
        #pragma unroll
        for (int i=0;i<16;i++) a1[i] = binit;

        #pragma unroll 4
        for (int k=0;k<128;k++) {
            const float* xrow = &XT(k,0);
            u64 wp = packdup(w1[(size_t)k*256 + c]);
            #pragma unroll
            for (int q=0;q<4;q++) {
                ulonglong2 qq = *(const ulonglong2*)(xrow + q*8);
                ulonglong2 qr = *(const ulonglong2*)(xrow + q*8 + 4);
                FMA_F32X2(a1[q*4+0], wp, qq.x, a1[q*4+0]);
                FMA_F32X2(a1[q*4+1], wp, qq.y, a1[q*4+1]);
                FMA_F32X2(a1[q*4+2], wp, qr.x, a1[q*4+2]);
                FMA_F32X2(a1[q*4+3], wp, qr.y, a1[q*4+3]);
            }
        }
        // gelu + store token-minor HT(c,t)
        #pragma unroll
        for (int i=0;i<16;i++) {
            float lo, hi;
            UNPACK_F32X2(lo, hi, a1[i]);
            HT(c, 2*i)   = 0.5f*lo*(1.f + erff(lo*0.70710678118654752f));
            HT(c, 2*i+1) = 0.5f*hi*(1.f + erff(hi*0.70710678118654752f));
        }
    }
    __syncthreads();

    // W2: i_c = col (0..127), jh = j-half; 16 pair accs each over 128 j
    const int i_c = tid & 127;
    const int jh  = tid >> 7;
    u64 a2[16];
    #pragma unroll
    for (int i=0;i<16;i++) a2[i] = 0ull;
    {
        const int j0 = jh * 128;
        #pragma unroll 4
        for (int jj=0;jj<128;jj++) {
            int j = j0 + jj;
            const float* hrow = &HT(j,0);
            u64 wp = packdup(w2[(size_t)j*128 + i_c]);
            #pragma unroll
            for (int q=0;q<4;q++) {
                ulonglong2 qq = *(const ulonglong2*)(hrow + q*8);
                ulonglong2 qr = *(const ulonglong2*)(hrow + q*8 + 4);
                FMA_F32X2(a2[q*4+0], wp, qq.x, a2[q*4+0]);
                FMA_F32X2(a2[q*4+1], wp, qq.y, a2[q*4+1]);
                FMA_F32X2(a2[q*4+2], wp, qr.x, a2[q*4+2]);
                FMA_F32X2(a2[q*4+3], wp, qr.y, a2[q*4+3]);
            }
        }
    }
    __syncthreads();                           // all reads of HT done

    // combine halves: jh=1 dumps partials into HT storage (reused as u64 buf)
    u64* pb = (u64*)&HT(0,0);                  // 128 cols * 16 pairs = 16 KB
    if (jh == 1) {
        #pragma unroll
        for (int ii=0;ii<16;ii++) pb[(size_t)i_c*16 + ii] = a2[ii];
    }
    __syncthreads();

    if (jh == 0) {
        float bb = b2[i_c];
        #pragma unroll
        for (int ii=0;ii<16;ii++) {
            float lo0, hi0, lo1, hi1;
            UNPACK_F32X2(lo0, hi0, a2[ii]);
            UNPACK_F32X2(lo1, hi1, pb[(size_t)i_c*16 + ii]);
            // y = x(LN1 out) + mlp + bias ; residual base XT(i_c, t)
            ZS(2*ii,   i_c) = XT(i_c, 2*ii)   + lo0 + lo1 + bb;
            ZS(2*ii+1, i_c) = XT(i_c, 2*ii+1) + hi0 + hi1 + bb;
        }
    }
    __syncthreads();

    // LN2 in-place on zs
    #pragma unroll
    for (int tt=0;tt<4;tt++) {
        int t = w*4 + tt;
        float vv[4];
        float sum=0.f, sq=0.f;
        #pragma unroll
        for (int j=0;j<4;j++) { vv[j] = ZS(t, lane + j*32); sum += vv[j]; sq += vv[j]*vv[j]; }
        #pragma unroll
        for (int o=16;o>0;o>>=1) {
            sum += __shfl_xor_sync(0xffffffffu,sum,o);
            sq  += __shfl_xor_sync(0xffffffffu,sq,o);
        }
        float mu = sum*(1.f/128.f);
        float var = sq*(1.f/128.f) - mu*mu;
        float rs = rsqrtf(var + EPS_LN);
        #pragma unroll
        for (int j=0;j<4;j++) {
            int k = lane + j*32;
            ZS(t,k) = (vv[j]-mu)*rs*ln2g[k] + ln2b[k];
        }
    }
    __syncthreads();

    // store transposed: out[b][dch][p0+t]; warp writes 32 consecutive floats
    float* ob = out + (size_t)b*DD*PP + p0;
    #pragma unroll
    for (int i2=0;i2<16;i2++) {
        int e = tid + i2*256;                 // e < 4096 = 128*32
        int dch = e >> 5, t = e & 31;
        ob[(size_t)dch*PP + t] = ZS(t,dch);
    }
}

// ---------------------------------------------------------------------------
extern "C" void kernel_launch(void* const* d_in, const int* in_sizes, int n_in,
                              void* d_out, int out_size)
{
    const float* feature   = (const float*)d_in[0];
    const float* I_src     = (const float*)d_in[1];
    const float* I_tar_inv = (const float*)d_in[2];
    const float* E         = (const float*)d_in[3];
    const float* dis       = (const float*)d_in[4];
    const float* norm_vec  = (const float*)d_in[5];
    const float* bn_gamma  = (const float*)d_in[6];
    const float* bn_beta   = (const float*)d_in[7];
    const float* bn_mean   = (const float*)d_in[8];
    const float* bn_var    = (const float*)d_in[9];
    const float* conv_w    = (const float*)d_in[10];
    const float* ln1_g     = (const float*)d_in[11];
    const float* ln1_b     = (const float*)d_in[12];
    const float* mlp_w1    = (const float*)d_in[13];
    const float* mlp_b1    = (const float*)d_in[14];
    const float* mlp_w2    = (const float*)d_in[15];
    const float* mlp_b2    = (const float*)d_in[16];
    const float* ln2_g     = (const float*)d_in[17];
    const float* ln2_b     = (const float*)d_in[18];
    float* out = (float*)d_out;

    const int mlp_smem = MLP_SMEM_FLOATS * 4;  // 71808 B
    cudaFuncSetAttribute(k_mlp, cudaFuncAttributeMaxDynamicSharedMemorySize, mlp_smem);

    k_hm<<<1, 32>>>(I_src, I_tar_inv, E, dis, norm_vec);
    k_conv<<<BB*NN*(PP/128), 256>>>(feature, conv_w, bn_gamma, bn_beta, bn_mean, bn_var);
    k_att<<<BB*PP/4, 256>>>();
    k_mlp<<<BB*(PP/TOK), 256, mlp_smem>>>(ln1_g, ln1_b, mlp_w1, mlp_b1, mlp_w2, mlp_b2,
                                          ln2_g, ln2_b, out);
}

// round 11
// speedup vs baseline: 1.0980x; 1.0980x over previous
#include <cuda_runtime.h>
#include <math.h>

// Problem constants
#define BB   4
#define NN   6
#define FD   256
#define DD   128
#define HF   64
#define WF   120
#define PP   (HF*WF)          // 7680
#define IMG_H 480.0f
#define IMG_W 960.0f
#define EPS_LN 1e-5f
#define EPS_BN 1e-5f

typedef unsigned long long u64;

// Packed fp32x2 FMA (sm_103a FFMA2 path; PTX-only, ptxas never auto-fuses)
#define FMA_F32X2(d, a, b, c) \
    asm("fma.rn.f32x2 %0, %1, %2, %3;" : "=l"(d) : "l"(a), "l"(b), "l"(c))
#define UNPACK_F32X2(lo, hi, in) \
    asm("mov.b64 {%0, %1}, %2;" : "=f"(lo), "=f"(hi) : "l"(in))

__device__ __forceinline__ u64 packdup(float x) {
    u64 r; asm("mov.b64 %0, {%1, %1};" : "=l"(r) : "f"(x)); return r;
}

// Scratch (device globals; no allocation allowed)
__device__ float g_val[(size_t)BB*NN*PP*DD];   // conv output, layout (b,n,p,d)  ~94.4 MB
__device__ float g_z  [(size_t)BB*PP*DD];      // attention output, layout (b,p,d) ~15.7 MB
__device__ float g_Hm [BB*NN*9];               // homographies

// ---------------------------------------------------------------------------
// Kernel 0: homography matrices Hm = I_src @ (R - T nv^T / dis) @ I_tar_inv
// ---------------------------------------------------------------------------
__global__ void k_hm(const float* __restrict__ I_src, const float* __restrict__ I_tar_inv,
                     const float* __restrict__ E, const float* __restrict__ dis_p,
                     const float* __restrict__ nv)
{
    int t = threadIdx.x;
    if (t >= BB*NN) return;
    int b = t / NN;
    const float* e  = E + (size_t)t*16;
    const float* nb = nv + (size_t)b*3;
    float dis = dis_p[0];

    float M[9];
    #pragma unroll
    for (int i=0;i<3;i++)
        #pragma unroll
        for (int j=0;j<3;j++)
            M[i*3+j] = e[i*4+j] - e[i*4+3]*nb[j]/dis;

    const float* Ti = I_tar_inv + (size_t)b*9;
    float A[9];
    #pragma unroll
    for (int i=0;i<3;i++)
        #pragma unroll
        for (int j=0;j<3;j++)
            A[i*3+j] = M[i*3+0]*Ti[0*3+j] + M[i*3+1]*Ti[1*3+j] + M[i*3+2]*Ti[2*3+j];

    const float* Is = I_src + (size_t)t*9;
    #pragma unroll
    for (int i=0;i<3;i++)
        #pragma unroll
        for (int j=0;j<3;j++)
            g_Hm[t*9 + i*3+j] = Is[i*3+0]*A[0*3+j] + Is[i*3+1]*A[1*3+j] + Is[i*3+2]*A[2*3+j];
}

// ---------------------------------------------------------------------------
// Kernel 1: val[b,n,p,o] = sum_f conv_w[o,f] * relu(bn(feature[b,n,f,p]))
// Tiled fp32 GEMM, FFMA2-packed over p-pairs; SOFTWARE-PIPELINED staging:
// next chunk's LDGs issue before the compute loop, hiding gmem latency.
// ---------------------------------------------------------------------------
__global__ __launch_bounds__(256) void k_conv(const float* __restrict__ feature,
                                              const float* __restrict__ conv_w,
                                              const float* __restrict__ bn_g,
                                              const float* __restrict__ bn_b,
                                              const float* __restrict__ bn_m,
                                              const float* __restrict__ bn_v)
{
    __shared__ float fs[16][128];        // [k][p]  8 KB
    __shared__ u64   ws2[16][129];       // [k][o] packed (w,w), pad=1  16.1 KB
    __shared__ float sc[FD], sh[FD];     // 2 KB

    const int blk   = blockIdx.x;             // 0 .. 24*60-1
    const int ptile = blk % (PP/128);         // 60 tiles
    const int bnidx = blk / (PP/128);         // b*NN + n
    const int p0    = ptile * 128;
    const int tid   = threadIdx.x;

    // BN scale/shift precompute: 256 threads cover FD=256 exactly
    {
        float s = bn_g[tid] * rsqrtf(bn_v[tid] + EPS_BN);
        sc[tid] = s;
        sh[tid] = bn_b[tid] - bn_m[tid] * s;
    }
    __syncthreads();

    const float* fbase = feature + (size_t)bnidx * FD * PP;
    const int to = (tid >> 4) * 8;    // o base
    const int tp = (tid & 15) * 8;    // p base (4 pairs)

    // fixed staging slots for this thread
    const int fr0 = tid >> 5;         // feature row 0..7 (and +8)
    const int fc4 = (tid & 31) * 4;   // feature col (float4)
    const int wo0 = tid >> 2;         // weight o 0..63 (and +64)
    const int wk4 = (tid & 3) * 4;    // weight k (float4)

    u64 acc2[4][8];                   // [p-pair][o]; each u64 = (p even, p odd)
    #pragma unroll
    for (int j=0;j<4;j++)
        #pragma unroll
        for (int i=0;i<8;i++) acc2[j][i] = 0ull;

    // prologue: prefetch chunk 0 into registers
    float4 fv0 = *(const float4*)(fbase + (size_t)fr0*PP     + p0 + fc4);
    float4 fv1 = *(const float4*)(fbase + (size_t)(fr0+8)*PP + p0 + fc4);
    float4 wv0 = *(const float4*)(conv_w + (size_t)wo0*FD      + wk4);
    float4 wv1 = *(const float4*)(conv_w + (size_t)(wo0+64)*FD + wk4);

    for (int kk=0; kk<FD; kk+=16) {
        // store staged regs -> smem (BN+ReLU at store time)
        {
            float s0 = sc[kk+fr0],   h0 = sh[kk+fr0];
            float4 v = fv0;
            v.x = fmaxf(v.x*s0 + h0, 0.f);
            v.y = fmaxf(v.y*s0 + h0, 0.f);
            v.z = fmaxf(v.z*s0 + h0, 0.f);
            v.w = fmaxf(v.w*s0 + h0, 0.f);
            *(float4*)&fs[fr0][fc4] = v;
            float s1 = sc[kk+fr0+8], h1 = sh[kk+fr0+8];
            float4 u = fv1;
            u.x = fmaxf(u.x*s1 + h1, 0.f);
            u.y = fmaxf(u.y*s1 + h1, 0.f);
            u.z = fmaxf(u.z*s1 + h1, 0.f);
            u.w = fmaxf(u.w*s1 + h1, 0.f);
            *(float4*)&fs[fr0+8][fc4] = u;
            ws2[wk4+0][wo0] = packdup(wv0.x);
            ws2[wk4+1][wo0] = packdup(wv0.y);
            ws2[wk4+2][wo0] = packdup(wv0.z);
            ws2[wk4+3][wo0] = packdup(wv0.w);
            ws2[wk4+0][wo0+64] = packdup(wv1.x);
            ws2[wk4+1][wo0+64] = packdup(wv1.y);
            ws2[wk4+2][wo0+64] = packdup(wv1.z);
            ws2[wk4+3][wo0+64] = packdup(wv1.w);
        }
        __syncthreads();

        // prefetch NEXT chunk while computing this one
        if (kk + 16 < FD) {
            int kn = kk + 16;
            fv0 = *(const float4*)(fbase + (size_t)(kn+fr0)*PP   + p0 + fc4);
            fv1 = *(const float4*)(fbase + (size_t)(kn+fr0+8)*PP + p0 + fc4);
            wv0 = *(const float4*)(conv_w + (size_t)wo0*FD      + kn + wk4);
            wv1 = *(const float4*)(conv_w + (size_t)(wo0+64)*FD + kn + wk4);
        }

        #pragma unroll
        for (int k=0;k<16;k++) {
            ulonglong2 fa = *(const ulonglong2*)&fs[k][tp];     // (p0,p1),(p2,p3)
            ulonglong2 fb = *(const ulonglong2*)&fs[k][tp+4];   // (p4,p5),(p6,p7)
            const u64* wrow = &ws2[k][to];
            #pragma unroll
            for (int i=0;i<8;i++) {
                u64 w2 = wrow[i];                               // LDS.64 broadcast
                FMA_F32X2(acc2[0][i], w2, fa.x, acc2[0][i]);
                FMA_F32X2(acc2[1][i], w2, fa.y, acc2[1][i]);
                FMA_F32X2(acc2[2][i], w2, fb.x, acc2[2][i]);
                FMA_F32X2(acc2[3][i], w2, fb.y, acc2[3][i]);
            }
        }
        __syncthreads();
    }

    // store: g_val[(bnidx*PP + p)*DD + o]; unpack pairs -> two rows per j
    float* obase = g_val + ((size_t)bnidx*PP + p0) * DD;
    #pragma unroll
    for (int j=0;j<4;j++) {
        float lo[8], hi[8];
        #pragma unroll
        for (int i=0;i<8;i++) { UNPACK_F32X2(lo[i], hi[i], acc2[j][i]); }
        float* row0 = obase + (size_t)(tp + 2*j    )*DD + to;
        float* row1 = obase + (size_t)(tp + 2*j + 1)*DD + to;
        *(float4*)(row0)   = make_float4(lo[0],lo[1],lo[2],lo[3]);
        *(float4*)(row0+4) = make_float4(lo[4],lo[5],lo[6],lo[7]);
        *(float4*)(row1)   = make_float4(hi[0],hi[1],hi[2],hi[3]);
        *(float4*)(row1+4) = make_float4(hi[4],hi[5],hi[6],hi[7]);
    }
}

// ---------------------------------------------------------------------------
// Kernel 2: homography warp + bilinear sample + cosine attention over N views
// 256-thread block = 4 pixels x 64 threads; each thread = channel PAIR (float2)
// ---------------------------------------------------------------------------
__global__ __launch_bounds__(256) void k_att()
{
    __shared__ float shm[NN*9];
    __shared__ float red[8][13];

    const int grp = threadIdx.x >> 6;          // pixel slot 0..3
    const int t64 = threadIdx.x & 63;          // channel-pair id
    const int pix = blockIdx.x*4 + grp;
    const int b = pix / PP;
    const int p = pix % PP;

    if (threadIdx.x < NN*9) shm[threadIdx.x] = g_Hm[b*NN*9 + threadIdx.x];
    __syncthreads();

    const int px = p % WF, py = p / WF;
    const float X = ((float)px / (float)(WF-1)) * IMG_W;
    const float Y = ((float)py / (float)(HF-1)) * IMG_H;

    const float2* vb2 = (const float2*)g_val + (size_t)b*NN*PP*(DD/2);
    const float2 qv = vb2[(size_t)p*(DD/2) + t64];   // view 0 = query

    float2 s2[NN];
    float validf[NN];

    #pragma unroll
    for (int n=0;n<NN;n++) {
        const float* Hh = shm + n*9;
        float hx = Hh[0]*X + Hh[1]*Y + Hh[2];
        float hy = Hh[3]*X + Hh[4]*Y + Hh[5];
        float hz = Hh[6]*X + Hh[7]*Y + Hh[8];
        float inv = 1.0f / hz;
        float u = (hx*inv) * ((float)WF / IMG_W);
        float v = (hy*inv) * ((float)HF / IMG_H);

        float x0 = floorf(u), y0 = floorf(v);
        float ax = 0.f, ay = 0.f;
        #pragma unroll
        for (int dx=0;dx<2;dx++) {
            #pragma unroll
            for (int dy=0;dy<2;dy++) {
                float cx = x0 + (float)dx, cy = y0 + (float)dy;
                float wgt = (1.0f - fabsf(u-cx)) * (1.0f - fabsf(v-cy));
                bool inb = (cx >= 0.f) && (cx <= (float)(WF-1)) &&
                           (cy >= 0.f) && (cy <= (float)(HF-1));
                int icx = (int)fminf(fmaxf(cx,0.f),(float)(WF-1));
                int icy = (int)fminf(fmaxf(cy,0.f),(float)(HF-1));
                float2 g = vb2[((size_t)n*PP + icy*WF + icx)*(DD/2) + t64];
                float wf = inb ? wgt : 0.f;
                ax += g.x * wf;
                ay += g.y * wf;
            }
        }
        s2[n] = make_float2(ax, ay);
        validf[n] = ((u >= 0.f) && (u <= (float)(WF-1)) &&
                     (v >= 0.f) && (v <= (float)(HF-1))) ? 1.f : 0.f;
    }

    // batched reduction of 13 quantities over the pixel's 64 threads:
    // [0..5] = sum s_n^2 ; [6..11] = sum qv*s_n ; [12] = sum qv^2
    float part[13];
    #pragma unroll
    for (int n=0;n<NN;n++) {
        part[n]   = s2[n].x*s2[n].x + s2[n].y*s2[n].y;
        part[6+n] = qv.x*s2[n].x   + qv.y*s2[n].y;
    }
    part[12] = qv.x*qv.x + qv.y*qv.y;

    #pragma unroll
    for (int o=16;o>0;o>>=1)
        #pragma unroll
        for (int i=0;i<13;i++)
            part[i] += __shfl_xor_sync(0xffffffffu, part[i], o);

    const int wid = threadIdx.x >> 5;          // 2*grp + warp-in-pixel
    if ((threadIdx.x & 31) == 0)
        #pragma unroll
        for (int i=0;i<13;i++) red[wid][i] = part[i];
    __syncthreads();

    float tot[13];
    #pragma unroll
    for (int i=0;i<13;i++)
        tot[i] = red[2*grp][i] + red[2*grp+1][i];

    const float qn = fmaxf(sqrtf(tot[12]), 1e-12f);
    float dotv[NN];
    #pragma unroll
    for (int n=0;n<NN;n++) {
        float nn = fmaxf(sqrtf(tot[n]), 1e-12f);
        dotv[n] = (tot[6+n] / (qn*nn)) * validf[n];
    }
    float m = dotv[0];
    #pragma unroll
    for (int n=1;n<NN;n++) m = fmaxf(m, dotv[n]);
    float esum = 0.f, e[NN];
    #pragma unroll
    for (int n=0;n<NN;n++) { e[n] = expf(dotv[n]-m); esum += e[n]; }
    float inv_es = 1.0f / esum;

    float zx = qv.x, zy = qv.y;
    #pragma unroll
    for (int n=0;n<NN;n++) {
        float a = e[n]*inv_es;
        zx += a*s2[n].x;
        zy += a*s2[n].y;
    }

    float2* gz2 = (float2*)g_z;
    gz2[((size_t)b*PP + p)*(DD/2) + t64] = make_float2(zx, zy);
}

// ---------------------------------------------------------------------------
// Kernel 3: LN1 -> MLP(128->256 gelu ->128) + residual(from LN1 out) -> LN2
// Token-minor shared layouts; 16 tokens/block, 256 threads.
// (Round-8 version restored: TOK=32 regressed — occupancy/register bound.)
// ---------------------------------------------------------------------------
#define TOK 16
#define TPAD 20   // row stride (floats) for token-minor arrays, 16B aligned
__global__ __launch_bounds__(256) void k_mlp(const float* __restrict__ ln1g,
                                             const float* __restrict__ ln1b,
                                             const float* __restrict__ w1,
                                             const float* __restrict__ b1,
                                             const float* __restrict__ w2,
                                             const float* __restrict__ b2,
                                             const float* __restrict__ ln2g,
                                             const float* __restrict__ ln2b,
                                             float* __restrict__ out)
{
    __shared__ float zs[TOK][129];      // token-major: input z; later y
    __shared__ float xt[128][TPAD];     // [k][t] LN1 output (residual base)
    __shared__ float ht[256][TPAD];     // [j][t] gelu output; later partial buf

    const int blk = blockIdx.x;               // b*(PP/TOK)+chunk
    const int b   = blk / (PP/TOK);
    const int p0  = (blk % (PP/TOK)) * TOK;
    const int tid = threadIdx.x;
    const int lane = tid & 31, w = tid >> 5;  // 8 warps

    const float* zbase = g_z + ((size_t)b*PP + p0) * DD;
    #pragma unroll
    for (int i=0;i<8;i++) {                   // 2048 elems / 256 threads
        int e = tid + i*256;
        int t = e >> 7, k = e & 127;
        zs[t][k] = zbase[(size_t)t*DD + k];
    }
    __syncthreads();

    // LN1: warp w -> tokens 2w, 2w+1; write token-minor xt[k][t]
    #pragma unroll
    for (int tt=0;tt<2;tt++) {
        int t = w*2 + tt;
        float sum=0.f, sq=0.f;
        #pragma unroll
        for (int j=0;j<4;j++) { float v = zs[t][lane + j*32]; sum += v; sq += v*v; }
        #pragma unroll
        for (int o=16;o>0;o>>=1) {
            sum += __shfl_xor_sync(0xffffffffu,sum,o);
            sq  += __shfl_xor_sync(0xffffffffu,sq,o);
        }
        float mu = sum*(1.f/128.f);
        float var = sq*(1.f/128.f) - mu*mu;
        float rs = rsqrtf(var + EPS_LN);
        #pragma unroll
        for (int j=0;j<4;j++) {
            int k = lane + j*32;
            xt[k][t] = (zs[t][k]-mu)*rs*ln1g[k] + ln1b[k];
        }
    }
    __syncthreads();

    // W1: thread = col c; 8 token-pair FFMA2 accumulators
    {
        const int c = tid;
        u64 a1[8];
        u64 binit = packdup(b1[c]);
        #pragma unroll
        for (int i=0;i<8;i++) a1[i] = binit;

        #pragma unroll 4
        for (int k=0;k<128;k++) {
            ulonglong2 q0 = *(const ulonglong2*)&xt[k][0];   // tokens 0-3
            ulonglong2 q1 = *(const ulonglong2*)&xt[k][4];   // tokens 4-7
            ulonglong2 q2 = *(const ulonglong2*)&xt[k][8];   // tokens 8-11
            ulonglong2 q3 = *(const ulonglong2*)&xt[k][12];  // tokens 12-15
            u64 wp = packdup(w1[(size_t)k*256 + c]);
            FMA_F32X2(a1[0], wp, q0.x, a1[0]);
            FMA_F32X2(a1[1], wp, q0.y, a1[1]);
            FMA_F32X2(a1[2], wp, q1.x, a1[2]);
            FMA_F32X2(a1[3], wp, q1.y, a1[3]);
            FMA_F32X2(a1[4], wp, q2.x, a1[4]);
            FMA_F32X2(a1[5], wp, q2.y, a1[5]);
            FMA_F32X2(a1[6], wp, q3.x, a1[6]);
            FMA_F32X2(a1[7], wp, q3.y, a1[7]);
        }
        // gelu + store token-minor ht[c][t]
        #pragma unroll
        for (int i=0;i<8;i++) {
            float lo, hi;
            UNPACK_F32X2(lo, hi, a1[i]);
            ht[c][2*i]   = 0.5f*lo*(1.f + erff(lo*0.70710678118654752f));
            ht[c][2*i+1] = 0.5f*hi*(1.f + erff(hi*0.70710678118654752f));
        }
    }
    __syncthreads();

    // W2: i = col (0..127), jh = which half of j-range; 8 pair accs each
    const int i_c = tid & 127;
    const int jh  = tid >> 7;
    u64 a2[8];
    #pragma unroll
    for (int i=0;i<8;i++) a2[i] = 0ull;
    {
        const int j0 = jh * 128;
        #pragma unroll 4
        for (int jj=0;jj<128;jj++) {
            int j = j0 + jj;
            ulonglong2 q0 = *(const ulonglong2*)&ht[j][0];
            ulonglong2 q1 = *(const ulonglong2*)&ht[j][4];
            ulonglong2 q2 = *(const ulonglong2*)&ht[j][8];
            ulonglong2 q3 = *(const ulonglong2*)&ht[j][12];
            u64 wp = packdup(w2[(size_t)j*128 + i_c]);
            FMA_F32X2(a2[0], wp, q0.x, a2[0]);
            FMA_F32X2(a2[1], wp, q0.y, a2[1]);
            FMA_F32X2(a2[2], wp, q1.x, a2[2]);
            FMA_F32X2(a2[3], wp, q1.y, a2[3]);
            FMA_F32X2(a2[4], wp, q2.x, a2[4]);
            FMA_F32X2(a2[5], wp, q2.y, a2[5]);
            FMA_F32X2(a2[6], wp, q3.x, a2[6]);
            FMA_F32X2(a2[7], wp, q3.y, a2[7]);
        }
    }
    __syncthreads();                           // all reads of ht done

    // combine halves: jh=1 dumps partials into ht storage (reused as u64 buf)
    u64* pb = (u64*)&ht[0][0];                 // 128 cols * 8 pairs = 8 KB
    if (jh == 1) {
        #pragma unroll
        for (int ii=0;ii<8;ii++) pb[(size_t)i_c*8 + ii] = a2[ii];
    }
    __syncthreads();

    if (jh == 0) {
        float bb = b2[i_c];
        #pragma unroll
        for (int ii=0;ii<8;ii++) {
            float lo0, hi0, lo1, hi1;
            UNPACK_F32X2(lo0, hi0, a2[ii]);
            UNPACK_F32X2(lo1, hi1, pb[(size_t)i_c*8 + ii]);
            // y = x(LN1 out) + mlp + bias ; residual base xt[i_c][t]
            zs[2*ii  ][i_c] = xt[i_c][2*ii  ] + lo0 + lo1 + bb;
            zs[2*ii+1][i_c] = xt[i_c][2*ii+1] + hi0 + hi1 + bb;
        }
    }
    __syncthreads();

    // LN2 in-place on zs
    #pragma unroll
    for (int tt=0;tt<2;tt++) {
        int t = w*2 + tt;
        float vv[4];
        float sum=0.f, sq=0.f;
        #pragma unroll
        for (int j=0;j<4;j++) { vv[j] = zs[t][lane + j*32]; sum += vv[j]; sq += vv[j]*vv[j]; }
        #pragma unroll
        for (int o=16;o>0;o>>=1) {
            sum += __shfl_xor_sync(0xffffffffu,sum,o);
            sq  += __shfl_xor_sync(0xffffffffu,sq,o);
        }
        float mu = sum*(1.f/128.f);
        float var = sq*(1.f/128.f) - mu*mu;
        float rs = rsqrtf(var + EPS_LN);
        #pragma unroll
        for (int j=0;j<4;j++) {
            int k = lane + j*32;
            zs[t][k] = (vv[j]-mu)*rs*ln2g[k] + ln2b[k];
        }
    }
    __syncthreads();

    // store transposed: out[b][dch][p0+t]
    float* ob = out + (size_t)b*DD*PP + p0;
    #pragma unroll
    for (int i2=0;i2<8;i2++) {
        int e = tid + i2*256;                 // e < 2048 = 128*16
        int dch = e >> 4, t = e & 15;
        ob[(size_t)dch*PP + t] = zs[t][dch];
    }
}

// ---------------------------------------------------------------------------
extern "C" void kernel_launch(void* const* d_in, const int* in_sizes, int n_in,
                              void* d_out, int out_size)
{
    const float* feature   = (const float*)d_in[0];
    const float* I_src     = (const float*)d_in[1];
    const float* I_tar_inv = (const float*)d_in[2];
    const float* E         = (const float*)d_in[3];
    const float* dis       = (const float*)d_in[4];
    const float* norm_vec  = (const float*)d_in[5];
    const float* bn_gamma  = (const float*)d_in[6];
    const float* bn_beta   = (const float*)d_in[7];
    const float* bn_mean   = (const float*)d_in[8];
    const float* bn_var    = (const float*)d_in[9];
    const float* conv_w    = (const float*)d_in[10];
    const float* ln1_g     = (const float*)d_in[11];
    const float* ln1_b     = (const float*)d_in[12];
    const float* mlp_w1    = (const float*)d_in[13];
    const float* mlp_b1    = (const float*)d_in[14];
    const float* mlp_w2    = (const float*)d_in[15];
    const float* mlp_b2    = (const float*)d_in[16];
    const float* ln2_g     = (const float*)d_in[17];
    const float* ln2_b     = (const float*)d_in[18];
    float* out = (float*)d_out;

    k_hm<<<1, 32>>>(I_src, I_tar_inv, E, dis, norm_vec);
    k_conv<<<BB*NN*(PP/128), 256>>>(feature, conv_w, bn_gamma, bn_beta, bn_mean, bn_var);
    k_att<<<BB*PP/4, 256>>>();
    k_mlp<<<BB*(PP/TOK), 256>>>(ln1_g, ln1_b, mlp_w1, mlp_b1, mlp_w2, mlp_b2,
                                ln2_g, ln2_b, out);
}

// round 12
// speedup vs baseline: 1.7036x; 1.5516x over previous
#include <cuda_runtime.h>
#include <math.h>
#include <stdint.h>

// Problem constants
#define BB   4
#define NN   6
#define FD   256
#define DD   128
#define HF   64
#define WF   120
#define PP   (HF*WF)          // 7680
#define IMG_H 480.0f
#define IMG_W 960.0f
#define EPS_LN 1e-5f
#define EPS_BN 1e-5f

typedef unsigned long long u64;

// Packed fp32x2 FMA (sm_103a FFMA2 path; PTX-only)
#define FMA_F32X2(d, a, b, c) \
    asm("fma.rn.f32x2 %0, %1, %2, %3;" : "=l"(d) : "l"(a), "l"(b), "l"(c))
#define UNPACK_F32X2(lo, hi, in) \
    asm("mov.b64 {%0, %1}, %2;" : "=f"(lo), "=f"(hi) : "l"(in))

__device__ __forceinline__ u64 packdup(float x) {
    u64 r; asm("mov.b64 %0, {%1, %1};" : "=l"(r) : "f"(x)); return r;
}
__device__ __forceinline__ uint32_t f2tf32(float f) {
    uint32_t r; asm("cvt.rna.tf32.f32 %0, %1;" : "=r"(r) : "f"(f)); return r;
}
// D += A(16x8,row) * B(8x8,col)  tf32, fp32 accum
#define MMA_TF32(d, a0,a1,a2,a3, b0,b1) \
    asm volatile("mma.sync.aligned.m16n8k8.row.col.f32.tf32.tf32.f32 " \
        "{%0,%1,%2,%3}, {%4,%5,%6,%7}, {%8,%9}, {%0,%1,%2,%3};" \
        : "+f"((d)[0]), "+f"((d)[1]), "+f"((d)[2]), "+f"((d)[3]) \
        : "r"(a0), "r"(a1), "r"(a2), "r"(a3), "r"(b0), "r"(b1))

// Scratch (device globals; no allocation allowed)
__device__ float g_val[(size_t)BB*NN*PP*DD];   // conv output, (b,n,p,d)
__device__ float g_z  [(size_t)BB*PP*DD];      // attention output, (b,p,d)
__device__ float g_Hm [BB*NN*9];               // homographies

// ---------------------------------------------------------------------------
// Kernel 0: homography matrices
// ---------------------------------------------------------------------------
__global__ void k_hm(const float* __restrict__ I_src, const float* __restrict__ I_tar_inv,
                     const float* __restrict__ E, const float* __restrict__ dis_p,
                     const float* __restrict__ nv)
{
    int t = threadIdx.x;
    if (t >= BB*NN) return;
    int b = t / NN;
    const float* e  = E + (size_t)t*16;
    const float* nb = nv + (size_t)b*3;
    float dis = dis_p[0];

    float M[9];
    #pragma unroll
    for (int i=0;i<3;i++)
        #pragma unroll
        for (int j=0;j<3;j++)
            M[i*3+j] = e[i*4+j] - e[i*4+3]*nb[j]/dis;

    const float* Ti = I_tar_inv + (size_t)b*9;
    float A[9];
    #pragma unroll
    for (int i=0;i<3;i++)
        #pragma unroll
        for (int j=0;j<3;j++)
            A[i*3+j] = M[i*3+0]*Ti[0*3+j] + M[i*3+1]*Ti[1*3+j] + M[i*3+2]*Ti[2*3+j];

    const float* Is = I_src + (size_t)t*9;
    #pragma unroll
    for (int i=0;i<3;i++)
        #pragma unroll
        for (int j=0;j<3;j++)
            g_Hm[t*9 + i*3+j] = Is[i*3+0]*A[0*3+j] + Is[i*3+1]*A[1*3+j] + Is[i*3+2]*A[2*3+j];
}

// ---------------------------------------------------------------------------
// Kernel 1: val[b,n,p,o] = sum_f conv_w[o,f] * relu(bn(feature[b,n,f,p]))
// tf32 tensor-core GEMM via mma.sync.m16n8k8. Block 128p x 128o, 8 warps
// (2x4), warp tile 64x32, K-chunk 32. Register-prefetch pipeline.
// smem row stride 36 words -> conflict-free fragment reads (bank = 4g+t).
// ---------------------------------------------------------------------------
__global__ __launch_bounds__(256) void k_conv(const float* __restrict__ feature,
                                              const float* __restrict__ conv_w,
                                              const float* __restrict__ bn_g,
                                              const float* __restrict__ bn_b,
                                              const float* __restrict__ bn_m,
                                              const float* __restrict__ bn_v)
{
    __shared__ uint32_t fs[128][36];     // [p][k] tf32 feature tile  18 KB
    __shared__ uint32_t ws[128][36];     // [o][k] tf32 weight tile   18 KB
    __shared__ float sc[FD], sh[FD];

    const int blk   = blockIdx.x;             // 0 .. 1439
    const int ptile = blk % (PP/128);
    const int bnidx = blk / (PP/128);
    const int p0    = ptile * 128;
    const int tid   = threadIdx.x;
    const int lane  = tid & 31, wid = tid >> 5;
    const int wm    = wid >> 2;               // 0..1 : p-offset wm*64
    const int wn    = wid & 3;                // 0..3 : o-offset wn*32
    const int g     = lane >> 2;              // groupID 0..7
    const int tg    = lane & 3;               // thread-in-group 0..3

    {
        float s = bn_g[tid] * rsqrtf(bn_v[tid] + EPS_BN);
        sc[tid] = s;
        sh[tid] = bn_b[tid] - bn_m[tid] * s;
    }
    __syncthreads();

    const float* fbase = feature + (size_t)bnidx * FD * PP;

    float acc[4][4][4];
    #pragma unroll
    for (int m=0;m<4;m++)
        #pragma unroll
        for (int n=0;n<4;n++)
            #pragma unroll
            for (int r=0;r<4;r++) acc[m][n][r] = 0.f;

    // staging register buffers
    float  fv[4][4];     // feature: item i -> (p, f4); 4 f-values for one p
    float4 wv[4];        // weights: item i -> (o, f4); float4 along f

    // prologue: prefetch chunk kk=0
    #pragma unroll
    for (int i=0;i<4;i++) {
        int e = tid + i*256, p = e & 127, f4 = e >> 7;
        #pragma unroll
        for (int j=0;j<4;j++)
            fv[i][j] = fbase[(size_t)(f4*4+j)*PP + p0 + p];
    }
    #pragma unroll
    for (int i=0;i<4;i++) {
        int e = tid + i*256, o = e >> 3, f4 = e & 7;
        wv[i] = *(const float4*)(conv_w + (size_t)o*FD + f4*4);
    }

    for (int kk=0; kk<FD; kk+=32) {
        // store staged -> smem with BN+ReLU+tf32 round
        #pragma unroll
        for (int i=0;i<4;i++) {
            int e = tid + i*256, p = e & 127, f4 = e >> 7;
            uint4 x;
            {
                int f = kk + f4*4;
                x.x = f2tf32(fmaxf(fv[i][0]*sc[f+0] + sh[f+0], 0.f));
                x.y = f2tf32(fmaxf(fv[i][1]*sc[f+1] + sh[f+1], 0.f));
                x.z = f2tf32(fmaxf(fv[i][2]*sc[f+2] + sh[f+2], 0.f));
                x.w = f2tf32(fmaxf(fv[i][3]*sc[f+3] + sh[f+3], 0.f));
            }
            *(uint4*)&fs[p][f4*4] = x;
        }
        #pragma unroll
        for (int i=0;i<4;i++) {
            int e = tid + i*256, o = e >> 3, f4 = e & 7;
            uint4 y;
            y.x = f2tf32(wv[i].x);
            y.y = f2tf32(wv[i].y);
            y.z = f2tf32(wv[i].z);
            y.w = f2tf32(wv[i].w);
            *(uint4*)&ws[o][f4*4] = y;
        }
        __syncthreads();

        // prefetch next chunk
        if (kk + 32 < FD) {
            int kn = kk + 32;
            #pragma unroll
            for (int i=0;i<4;i++) {
                int e = tid + i*256, p = e & 127, f4 = e >> 7;
                #pragma unroll
                for (int j=0;j<4;j++)
                    fv[i][j] = fbase[(size_t)(kn + f4*4+j)*PP + p0 + p];
            }
            #pragma unroll
            for (int i=0;i<4;i++) {
                int e = tid + i*256, o = e >> 3, f4 = e & 7;
                wv[i] = *(const float4*)(conv_w + (size_t)o*FD + kn + f4*4);
            }
        }

        // compute: 4 sub-k of 8
        #pragma unroll
        for (int k8s=0;k8s<4;k8s++) {
            const int k8 = k8s*8;
            uint32_t bf[4][2];
            #pragma unroll
            for (int n=0;n<4;n++) {
                int orow = wn*32 + n*8 + g;
                bf[n][0] = ws[orow][k8 + tg];
                bf[n][1] = ws[orow][k8 + tg + 4];
            }
            #pragma unroll
            for (int m=0;m<4;m++) {
                int pr = wm*64 + m*16 + g;
                uint32_t a0 = fs[pr    ][k8 + tg];
                uint32_t a1 = fs[pr + 8][k8 + tg];
                uint32_t a2 = fs[pr    ][k8 + tg + 4];
                uint32_t a3 = fs[pr + 8][k8 + tg + 4];
                #pragma unroll
                for (int n=0;n<4;n++)
                    MMA_TF32(acc[m][n], a0,a1,a2,a3, bf[n][0], bf[n][1]);
            }
        }
        __syncthreads();
    }

    // epilogue: g_val[(bnidx*PP + p)*DD + o]; float2 (32B-sector aligned)
    float* obase = g_val + ((size_t)bnidx*PP + p0) * DD;
    #pragma unroll
    for (int m=0;m<4;m++) {
        int p = wm*64 + m*16 + g;
        #pragma unroll
        for (int n=0;n<4;n++) {
            int o = wn*32 + n*8 + tg*2;
            *(float2*)&obase[(size_t)p*DD + o]     = make_float2(acc[m][n][0], acc[m][n][1]);
            *(float2*)&obase[(size_t)(p+8)*DD + o] = make_float2(acc[m][n][2], acc[m][n][3]);
        }
    }
}

// ---------------------------------------------------------------------------
// Kernel 2: homography warp + bilinear sample + cosine attention over N views
// 256-thread block = 4 pixels x 64 threads; thread = channel pair (float2)
// ---------------------------------------------------------------------------
__global__ __launch_bounds__(256) void k_att()
{
    __shared__ float shm[NN*9];
    __shared__ float red[8][13];

    const int grp = threadIdx.x >> 6;
    const int t64 = threadIdx.x & 63;
    const int pix = blockIdx.x*4 + grp;
    const int b = pix / PP;
    const int p = pix % PP;

    if (threadIdx.x < NN*9) shm[threadIdx.x] = g_Hm[b*NN*9 + threadIdx.x];
    __syncthreads();

    const int px = p % WF, py = p / WF;
    const float X = ((float)px / (float)(WF-1)) * IMG_W;
    const float Y = ((float)py / (float)(HF-1)) * IMG_H;

    const float2* vb2 = (const float2*)g_val + (size_t)b*NN*PP*(DD/2);
    const float2 qv = vb2[(size_t)p*(DD/2) + t64];

    float2 s2[NN];
    float validf[NN];

    #pragma unroll
    for (int n=0;n<NN;n++) {
        const float* Hh = shm + n*9;
        float hx = Hh[0]*X + Hh[1]*Y + Hh[2];
        float hy = Hh[3]*X + Hh[4]*Y + Hh[5];
        float hz = Hh[6]*X + Hh[7]*Y + Hh[8];
        float inv = 1.0f / hz;
        float u = (hx*inv) * ((float)WF / IMG_W);
        float v = (hy*inv) * ((float)HF / IMG_H);

        float x0 = floorf(u), y0 = floorf(v);
        float ax = 0.f, ay = 0.f;
        #pragma unroll
        for (int dx=0;dx<2;dx++) {
            #pragma unroll
            for (int dy=0;dy<2;dy++) {
                float cx = x0 + (float)dx, cy = y0 + (float)dy;
                float wgt = (1.0f - fabsf(u-cx)) * (1.0f - fabsf(v-cy));
                bool inb = (cx >= 0.f) && (cx <= (float)(WF-1)) &&
                           (cy >= 0.f) && (cy <= (float)(HF-1));
                int icx = (int)fminf(fmaxf(cx,0.f),(float)(WF-1));
                int icy = (int)fminf(fmaxf(cy,0.f),(float)(HF-1));
                float2 gg = vb2[((size_t)n*PP + icy*WF + icx)*(DD/2) + t64];
                float wf = inb ? wgt : 0.f;
                ax += gg.x * wf;
                ay += gg.y * wf;
            }
        }
        s2[n] = make_float2(ax, ay);
        validf[n] = ((u >= 0.f) && (u <= (float)(WF-1)) &&
                     (v >= 0.f) && (v <= (float)(HF-1))) ? 1.f : 0.f;
    }

    float part[13];
    #pragma unroll
    for (int n=0;n<NN;n++) {
        part[n]   = s2[n].x*s2[n].x + s2[n].y*s2[n].y;
        part[6+n] = qv.x*s2[n].x   + qv.y*s2[n].y;
    }
    part[12] = qv.x*qv.x + qv.y*qv.y;

    #pragma unroll
    for (int o=16;o>0;o>>=1)
        #pragma unroll
        for (int i=0;i<13;i++)
            part[i] += __shfl_xor_sync(0xffffffffu, part[i], o);

    const int wid = threadIdx.x >> 5;
    if ((threadIdx.x & 31) == 0)
        #pragma unroll
        for (int i=0;i<13;i++) red[wid][i] = part[i];
    __syncthreads();

    float tot[13];
    #pragma unroll
    for (int i=0;i<13;i++)
        tot[i] = red[2*grp][i] + red[2*grp+1][i];

    const float qn = fmaxf(sqrtf(tot[12]), 1e-12f);
    float dotv[NN];
    #pragma unroll
    for (int n=0;n<NN;n++) {
        float nn = fmaxf(sqrtf(tot[n]), 1e-12f);
        dotv[n] = (tot[6+n] / (qn*nn)) * validf[n];
    }
    float m = dotv[0];
    #pragma unroll
    for (int n=1;n<NN;n++) m = fmaxf(m, dotv[n]);
    float esum = 0.f, e[NN];
    #pragma unroll
    for (int n=0;n<NN;n++) { e[n] = expf(dotv[n]-m); esum += e[n]; }
    float inv_es = 1.0f / esum;

    float zx = qv.x, zy = qv.y;
    #pragma unroll
    for (int n=0;n<NN;n++) {
        float a = e[n]*inv_es;
        zx += a*s2[n].x;
        zy += a*s2[n].y;
    }

    float2* gz2 = (float2*)g_z;
    gz2[((size_t)b*PP + p)*(DD/2) + t64] = make_float2(zx, zy);
}

// ---------------------------------------------------------------------------
// Kernel 3: LN1 -> MLP -> residual(from LN1 out) -> LN2 (Round-8 version)
// ---------------------------------------------------------------------------
#define TOK 16
#define TPAD 20
__global__ __launch_bounds__(256) void k_mlp(const float* __restrict__ ln1g,
                                             const float* __restrict__ ln1b,
                                             const float* __restrict__ w1,
                                             const float* __restrict__ b1,
                                             const float* __restrict__ w2,
                                             const float* __restrict__ b2,
                                             const float* __restrict__ ln2g,
                                             const float* __restrict__ ln2b,
                                             float* __restrict__ out)
{
    __shared__ float zs[TOK][129];
    __shared__ float xt[128][TPAD];
    __shared__ float ht[256][TPAD];

    const int blk = blockIdx.x;
    const int b   = blk / (PP/TOK);
    const int p0  = (blk % (PP/TOK)) * TOK;
    const int tid = threadIdx.x;
    const int lane = tid & 31, w = tid >> 5;

    const float* zbase = g_z + ((size_t)b*PP + p0) * DD;
    #pragma unroll
    for (int i=0;i<8;i++) {
        int e = tid + i*256;
        int t = e >> 7, k = e & 127;
        zs[t][k] = zbase[(size_t)t*DD + k];
    }
    __syncthreads();

    #pragma unroll
    for (int tt=0;tt<2;tt++) {
        int t = w*2 + tt;
        float sum=0.f, sq=0.f;
        #pragma unroll
        for (int j=0;j<4;j++) { float v = zs[t][lane + j*32]; sum += v; sq += v*v; }
        #pragma unroll
        for (int o=16;o>0;o>>=1) {
            sum += __shfl_xor_sync(0xffffffffu,sum,o);
            sq  += __shfl_xor_sync(0xffffffffu,sq,o);
        }
        float mu = sum*(1.f/128.f);
        float var = sq*(1.f/128.f) - mu*mu;
        float rs = rsqrtf(var + EPS_LN);
        #pragma unroll
        for (int j=0;j<4;j++) {
            int k = lane + j*32;
            xt[k][t] = (zs[t][k]-mu)*rs*ln1g[k] + ln1b[k];
        }
    }
    __syncthreads();

    {
        const int c = tid;
        u64 a1[8];
        u64 binit = packdup(b1[c]);
        #pragma unroll
        for (int i=0;i<8;i++) a1[i] = binit;

        #pragma unroll 4
        for (int k=0;k<128;k++) {
            ulonglong2 q0 = *(const ulonglong2*)&xt[k][0];
            ulonglong2 q1 = *(const ulonglong2*)&xt[k][4];
            ulonglong2 q2 = *(const ulonglong2*)&xt[k][8];
            ulonglong2 q3 = *(const ulonglong2*)&xt[k][12];
            u64 wp = packdup(w1[(size_t)k*256 + c]);
            FMA_F32X2(a1[0], wp, q0.x, a1[0]);
            FMA_F32X2(a1[1], wp, q0.y, a1[1]);
            FMA_F32X2(a1[2], wp, q1.x, a1[2]);
            FMA_F32X2(a1[3], wp, q1.y, a1[3]);
            FMA_F32X2(a1[4], wp, q2.x, a1[4]);
            FMA_F32X2(a1[5], wp, q2.y, a1[5]);
            FMA_F32X2(a1[6], wp, q3.x, a1[6]);
            FMA_F32X2(a1[7], wp, q3.y, a1[7]);
        }
        #pragma unroll
        for (int i=0;i<8;i++) {
            float lo, hi;
            UNPACK_F32X2(lo, hi, a1[i]);
            ht[c][2*i]   = 0.5f*lo*(1.f + erff(lo*0.70710678118654752f));
            ht[c][2*i+1] = 0.5f*hi*(1.f + erff(hi*0.70710678118654752f));
        }
    }
    __syncthreads();

    const int i_c = tid & 127;
    const int jh  = tid >> 7;
    u64 a2[8];
    #pragma unroll
    for (int i=0;i<8;i++) a2[i] = 0ull;
    {
        const int j0 = jh * 128;
        #pragma unroll 4
        for (int jj=0;jj<128;jj++) {
            int j = j0 + jj;
            ulonglong2 q0 = *(const ulonglong2*)&ht[j][0];
            ulonglong2 q1 = *(const ulonglong2*)&ht[j][4];
            ulonglong2 q2 = *(const ulonglong2*)&ht[j][8];
            ulonglong2 q3 = *(const ulonglong2*)&ht[j][12];
            u64 wp = packdup(w2[(size_t)j*128 + i_c]);
            FMA_F32X2(a2[0], wp, q0.x, a2[0]);
            FMA_F32X2(a2[1], wp, q0.y, a2[1]);
            FMA_F32X2(a2[2], wp, q1.x, a2[2]);
            FMA_F32X2(a2[3], wp, q1.y, a2[3]);
            FMA_F32X2(a2[4], wp, q2.x, a2[4]);
            FMA_F32X2(a2[5], wp, q2.y, a2[5]);
            FMA_F32X2(a2[6], wp, q3.x, a2[6]);
            FMA_F32X2(a2[7], wp, q3.y, a2[7]);
        }
    }
    __syncthreads();

    u64* pb = (u64*)&ht[0][0];
    if (jh == 1) {
        #pragma unroll
        for (int ii=0;ii<8;ii++) pb[(size_t)i_c*8 + ii] = a2[ii];
    }
    __syncthreads();

    if (jh == 0) {
        float bb = b2[i_c];
        #pragma unroll
        for (int ii=0;ii<8;ii++) {
            float lo0, hi0, lo1, hi1;
            UNPACK_F32X2(lo0, hi0, a2[ii]);
            UNPACK_F32X2(lo1, hi1, pb[(size_t)i_c*8 + ii]);
            zs[2*ii  ][i_c] = xt[i_c][2*ii  ] + lo0 + lo1 + bb;
            zs[2*ii+1][i_c] = xt[i_c][2*ii+1] + hi0 + hi1 + bb;
        }
    }
    __syncthreads();

    #pragma unroll
    for (int tt=0;tt<2;tt++) {
        int t = w*2 + tt;
        float vv[4];
        float sum=0.f, sq=0.f;
        #pragma unroll
        for (int j=0;j<4;j++) { vv[j] = zs[t][lane + j*32]; sum += vv[j]; sq += vv[j]*vv[j]; }
        #pragma unroll
        for (int o=16;o>0;o>>=1) {
            sum += __shfl_xor_sync(0xffffffffu,sum,o);
            sq  += __shfl_xor_sync(0xffffffffu,sq,o);
        }
        float mu = sum*(1.f/128.f);
        float var = sq*(1.f/128.f) - mu*mu;
        float rs = rsqrtf(var + EPS_LN);
        #pragma unroll
        for (int j=0;j<4;j++) {
            int k = lane + j*32;
            zs[t][k] = (vv[j]-mu)*rs*ln2g[k] + ln2b[k];
        }
    }
    __syncthreads();

    float* ob = out + (size_t)b*DD*PP + p0;
    #pragma unroll
    for (int i2=0;i2<8;i2++) {
        int e = tid + i2*256;
        int dch = e >> 4, t = e & 15;
        ob[(size_t)dch*PP + t] = zs[t][dch];
    }
}

// ---------------------------------------------------------------------------
extern "C" void kernel_launch(void* const* d_in, const int* in_sizes, int n_in,
                              void* d_out, int out_size)
{
    const float* feature   = (const float*)d_in[0];
    const float* I_src     = (const float*)d_in[1];
    const float* I_tar_inv = (const float*)d_in[2];
    const float* E         = (const float*)d_in[3];
    const float* dis       = (const float*)d_in[4];
    const float* norm_vec  = (const float*)d_in[5];
    const float* bn_gamma  = (const float*)d_in[6];
    const float* bn_beta   = (const float*)d_in[7];
    const float* bn_mean   = (const float*)d_in[8];
    const float* bn_var    = (const float*)d_in[9];
    const float* conv_w    = (const float*)d_in[10];
    const float* ln1_g     = (const float*)d_in[11];
    const float* ln1_b     = (const float*)d_in[12];
    const float* mlp_w1    = (const float*)d_in[13];
    const float* mlp_b1    = (const float*)d_in[14];
    const float* mlp_w2    = (const float*)d_in[15];
    const float* mlp_b2    = (const float*)d_in[16];
    const float* ln2_g     = (const float*)d_in[17];
    const float* ln2_b     = (const float*)d_in[18];
    float* out = (float*)d_out;

    k_hm<<<1, 32>>>(I_src, I_tar_inv, E, dis, norm_vec);
    k_conv<<<BB*NN*(PP/128), 256>>>(feature, conv_w, bn_gamma, bn_beta, bn_mean, bn_var);
    k_att<<<BB*PP/4, 256>>>();
    k_mlp<<<BB*(PP/TOK), 256>>>(ln1_g, ln1_b, mlp_w1, mlp_b1, mlp_w2, mlp_b2,
                                ln2_g, ln2_b, out);
}